// round 15
// baseline (speedup 1.0000x reference)
#include <cuda_runtime.h>
#include <cuda_fp16.h>
#include <math.h>
#include <cstdint>

#define BATCH   2
#define S_LEN   2048
#define D_MODEL 2048
#define NHEADS  32
#define NKVH    8
#define HDIM    64
#define GSIZE   (NHEADS / NKVH)
#define KVD     (NKVH * HDIM)        // 512
#define MROWS   (BATCH * S_LEN)      // 4096
#define KDIM    2048
#define NKV2    (2 * KVD)            // 1024 fused K|V width

// ---------------- scratch (device globals) ----------------------------------
__device__ __half g_ahat[(size_t)MROWS * KDIM];     // x fp16
__device__ __half g_chat[(size_t)MROWS * KDIM];     // ctx fp16
__device__ __half g_wq [(size_t)KDIM * D_MODEL];    // k-major [K][N]
__device__ __half g_wkv[(size_t)KDIM * NKV2];       // k-major [K][Nk|Nv]
__device__ __half g_wo [(size_t)KDIM * D_MODEL];    // k-major
__device__ float g_cos[S_LEN * 32];
__device__ float g_sin[S_LEN * 32];
__device__ __half g_q16[MROWS * D_MODEL];
__device__ __half g_khi[MROWS * KVD];
__device__ __half g_vhi[MROWS * KVD];

// ---------------- helpers ------------------------------------------------
__device__ __forceinline__ uint32_t smem_u32(const void* p) {
    uint32_t a;
    asm("{ .reg .u64 t; cvta.to.shared.u64 t, %1; cvt.u32.u64 %0, t; }"
        : "=r"(a) : "l"(p));
    return a;
}

__device__ __forceinline__ void cp16(uint32_t saddr, const void* gaddr) {
    asm volatile("cp.async.cg.shared.global [%0], [%1], 16;"
                 :: "r"(saddr), "l"(gaddr) : "memory");
}
#define CP_COMMIT() asm volatile("cp.async.commit_group;" ::: "memory")
#define CP_WAIT(n)  asm volatile("cp.async.wait_group %0;" :: "n"(n) : "memory")

__device__ __forceinline__ void ldsm4(uint32_t& r0, uint32_t& r1, uint32_t& r2,
                                      uint32_t& r3, uint32_t addr) {
    asm volatile("ldmatrix.sync.aligned.m8n8.x4.shared.b16 {%0,%1,%2,%3}, [%4];"
                 : "=r"(r0), "=r"(r1), "=r"(r2), "=r"(r3) : "r"(addr));
}
__device__ __forceinline__ void ldsm4t(uint32_t& r0, uint32_t& r1, uint32_t& r2,
                                       uint32_t& r3, uint32_t addr) {
    asm volatile("ldmatrix.sync.aligned.m8n8.x4.trans.shared.b16 {%0,%1,%2,%3}, [%4];"
                 : "=r"(r0), "=r"(r1), "=r"(r2), "=r"(r3) : "r"(addr));
}

__device__ __forceinline__ void mma16816(float* d, const uint32_t* a, const uint32_t* b) {
    asm volatile(
        "mma.sync.aligned.m16n8k16.row.col.f32.f16.f16.f32 "
        "{%0,%1,%2,%3}, {%4,%5,%6,%7}, {%8,%9}, {%0,%1,%2,%3};"
        : "+f"(d[0]), "+f"(d[1]), "+f"(d[2]), "+f"(d[3])
        : "r"(a[0]), "r"(a[1]), "r"(a[2]), "r"(a[3]), "r"(b[0]), "r"(b[1]));
}

__device__ __forceinline__ uint32_t pack2h(float lo_e, float hi_e) {
    __half2 h = __floats2half2_rn(lo_e, hi_e);
    return *reinterpret_cast<uint32_t*>(&h);
}

// ---------------- streaming prep kernel ---------------------------------------
// ranges (blocks of 256): x conv | rope table | wq | wkv | wo
#define PB_X    32768                        // 8,388,608 elems
#define PB_ROPE (PB_X + 256)
#define PB_WQ   (PB_ROPE + 16384)            // 4,194,304
#define PB_WKV  (PB_WQ + 8192)               // 2,097,152
#define PB_WO   (PB_WKV + 16384)
#define PREP_BLOCKS PB_WO

__global__ __launch_bounds__(256)
void prep(const float* __restrict__ x,
          const float* __restrict__ Wq, const float* __restrict__ Wk,
          const float* __restrict__ Wv, const float* __restrict__ Wo,
          __half* __restrict__ ahat, __half* __restrict__ wq,
          __half* __restrict__ wkv, __half* __restrict__ wo)
{
    const int bid = blockIdx.x;
    const int tid = threadIdx.x;

    if (bid < PB_X) {
        int i = bid * 256 + tid;
        ahat[i] = __float2half_rn(x[i]);
    } else if (bid < PB_ROPE) {
        int i = (bid - PB_X) * 256 + tid;
        int s = i >> 5, j = i & 31;
        float inv = (float)exp(-(double)j * (log(10000.0) / 32.0));
        float ang = (float)s * inv;
        float c, sn;
        sincosf(ang, &sn, &c);
        g_cos[i] = c;
        g_sin[i] = sn;
    } else if (bid < PB_WQ) {
        int i = (bid - PB_ROPE) * 256 + tid;
        wq[i] = __float2half_rn(Wq[i]);
    } else if (bid < PB_WKV) {
        int i = (bid - PB_WQ) * 256 + tid;
        int k = i >> 10, n = i & 1023;
        float v = (n < KVD) ? Wk[(k << 9) + n] : Wv[(k << 9) + n - KVD];
        wkv[i] = __float2half_rn(v);
    } else {
        int i = (bid - PB_WKV) * 256 + tid;
        wo[i] = __float2half_rn(Wo[i]);
    }
}

// ---------------- GEMM core ----------------------------------------------------
// 128x128 CTA, 4 warps (2M x 2N), warp tile 64x64, KC=64, 3 stages, 128 threads.
// A: m-major rows [128][KC] (144B rows); B: k-major rows [KC][128] (272B rows),
// fragments via ldsm4t (proven pattern from attention PV path).
#define BM 128
#define BN 128
#define KC 64
#define STAGES 3
#define RSA    144
#define RSB2   272
#define STG_A  (128 * RSA)           // 18432
#define STG_B  (KC * RSB2)           // 17408
#define STG_SZ (STG_A + STG_B)       // 35840
#define GSMEM  (STAGES * STG_SZ)     // 107520
#define GTHREADS 128

__device__ __forceinline__ void gemm_core(
    const __half* __restrict__ Ab, const __half* __restrict__ Bb, int NW,
    uint32_t sbase, int tid, int lane, int wm, int wn, float acc[4][8][4])
{
    constexpr int NCHUNK = KDIM / KC;

    const int a_row  = wm + (lane & 15);
    const int a_koff = ((lane >> 4) & 1) * 8;
    // B ldsm4t lane addressing (k-major tile): row = k, col = n
    const int b_krow = (lane & 7) + ((lane >> 3) & 1) * 8;
    const int b_noff = wn + ((lane >> 4) & 1) * 8;

    auto fill = [&](int c, int slot) {
        const int kpos = c * KC;
        const uint32_t abase = sbase + slot * STG_SZ;
        const uint32_t bbase = abase + STG_A;
        // A: 128 rows x 8 segs(16B) = 1024 units
        #pragma unroll
        for (int i = 0; i < 8; i++) {
            int u = tid + GTHREADS * i;
            int row = u >> 3, seg = u & 7;
            cp16(abase + row * RSA + seg * 16, Ab + (size_t)row * KDIM + kpos + seg * 8);
        }
        // B: 64 k-rows x 16 segs(16B) = 1024 units
        #pragma unroll
        for (int i = 0; i < 8; i++) {
            int u = tid + GTHREADS * i;
            int row = u >> 4, seg = u & 15;
            cp16(bbase + row * RSB2 + seg * 16, Bb + (size_t)(kpos + row) * NW + seg * 8);
        }
    };

    #pragma unroll
    for (int s = 0; s < STAGES - 1; s++) {
        fill(s, s);
        CP_COMMIT();
    }

    for (int c = 0; c < NCHUNK; c++) {
        CP_WAIT(STAGES - 2);
        __syncthreads();

        if (c + STAGES - 1 < NCHUNK)
            fill(c + STAGES - 1, (c + STAGES - 1) % STAGES);
        CP_COMMIT();

        const int slot = c % STAGES;
        const uint32_t abase = sbase + slot * STG_SZ;
        const uint32_t bbase = abase + STG_A;
        #pragma unroll
        for (int ks = 0; ks < 4; ks++) {
            const int kp = ks * 16;
            uint32_t af[4][4];
            #pragma unroll
            for (int mt = 0; mt < 4; mt++) {
                uint32_t addr = abase + (a_row + mt * 16) * RSA + (kp + a_koff) * 2;
                ldsm4(af[mt][0], af[mt][1], af[mt][2], af[mt][3], addr);
            }
            uint32_t bf[8][2];
            #pragma unroll
            for (int g = 0; g < 4; g++) {
                uint32_t addr = bbase + (kp + b_krow) * RSB2 + (b_noff + g * 16) * 2;
                ldsm4t(bf[2*g][0], bf[2*g][1], bf[2*g+1][0], bf[2*g+1][1], addr);
            }
            #pragma unroll
            for (int mt = 0; mt < 4; mt++)
                #pragma unroll
                for (int nt = 0; nt < 8; nt++)
                    mma16816(acc[mt][nt], af[mt], bf[nt]);
        }
    }
}

// ---------------- fused QKV projection kernel --------------------------------
__global__ __launch_bounds__(GTHREADS)
void qkv_gemm(const __half* __restrict__ A,
              const __half* __restrict__ Wq, const __half* __restrict__ Wkv,
              __half* __restrict__ q16,
              __half* __restrict__ khi, __half* __restrict__ vhi)
{
    extern __shared__ char gsm[];
    const uint32_t sbase = smem_u32(gsm);

    const int tid  = threadIdx.x;
    const int wid  = tid >> 5;
    const int lane = tid & 31;
    const int bm   = blockIdx.y * BM;
    const bool isQ = blockIdx.x < (D_MODEL / BN);
    const int bn   = (isQ ? blockIdx.x : blockIdx.x - D_MODEL / BN) * BN;
    const int wm   = (wid & 1) * 64;
    const int wn   = (wid >> 1) * 64;

    float acc[4][8][4];
    #pragma unroll
    for (int i = 0; i < 4; i++)
        #pragma unroll
        for (int j = 0; j < 8; j++)
            #pragma unroll
            for (int t = 0; t < 4; t++) acc[i][j][t] = 0.f;

    const __half* Ab = A + (size_t)bm * KDIM;
    const __half* Bb = (isQ ? Wq : Wkv) + bn;
    const int NW = isQ ? D_MODEL : NKV2;

    gemm_core(Ab, Bb, NW, sbase, tid, lane, wm, wn, acc);

    const int cr = lane >> 2;
    const int cc = (lane & 3) * 2;

    if (isQ) {
        const int head = (bn + wn) >> 6;
        #pragma unroll
        for (int mt = 0; mt < 4; mt++) {
            #pragma unroll
            for (int r = 0; r < 2; r++) {
                const int row = bm + wm + mt * 16 + cr + r * 8;
                const int s = row & (S_LEN - 1);
                #pragma unroll
                for (int nt = 0; nt < 4; nt++) {
                    const int j = nt * 8 + cc;
                    float c0 = g_cos[(s << 5) + j],     sn0 = g_sin[(s << 5) + j];
                    float c1 = g_cos[(s << 5) + j + 1], sn1 = g_sin[(s << 5) + j + 1];
                    float x1a = acc[mt][nt][2*r],     x1b = acc[mt][nt][2*r + 1];
                    float x2a = acc[mt][nt+4][2*r],   x2b = acc[mt][nt+4][2*r + 1];
                    float y1a = (x1a * c0 - x2a * sn0) * 0.125f;
                    float y1b = (x1b * c1 - x2b * sn1) * 0.125f;
                    float y2a = (x2a * c0 + x1a * sn0) * 0.125f;
                    float y2b = (x2b * c1 + x1b * sn1) * 0.125f;
                    size_t off = (size_t)row * D_MODEL + head * HDIM + j;
                    *reinterpret_cast<__half2*>(q16 + off)      = __floats2half2_rn(y1a, y1b);
                    *reinterpret_cast<__half2*>(q16 + off + 32) = __floats2half2_rn(y2a, y2b);
                }
            }
        }
    } else {
        const int hh = (bn + wn) >> 6;
        if (hh < NKVH) {
            #pragma unroll
            for (int mt = 0; mt < 4; mt++) {
                #pragma unroll
                for (int r = 0; r < 2; r++) {
                    const int row = bm + wm + mt * 16 + cr + r * 8;
                    const int s = row & (S_LEN - 1);
                    #pragma unroll
                    for (int nt = 0; nt < 4; nt++) {
                        const int j = nt * 8 + cc;
                        float c0 = g_cos[(s << 5) + j],     sn0 = g_sin[(s << 5) + j];
                        float c1 = g_cos[(s << 5) + j + 1], sn1 = g_sin[(s << 5) + j + 1];
                        float x1a = acc[mt][nt][2*r],   x1b = acc[mt][nt][2*r + 1];
                        float x2a = acc[mt][nt+4][2*r], x2b = acc[mt][nt+4][2*r + 1];
                        size_t off = (size_t)row * KVD + hh * HDIM + j;
                        *reinterpret_cast<__half2*>(khi + off) =
                            __floats2half2_rn(x1a * c0 - x2a * sn0, x1b * c1 - x2b * sn1);
                        *reinterpret_cast<__half2*>(khi + off + 32) =
                            __floats2half2_rn(x2a * c0 + x1a * sn0, x2b * c1 + x1b * sn1);
                    }
                }
            }
        } else {
            const int vh = hh - NKVH;
            #pragma unroll
            for (int mt = 0; mt < 4; mt++) {
                #pragma unroll
                for (int r = 0; r < 2; r++) {
                    const int row = bm + wm + mt * 16 + cr + r * 8;
                    #pragma unroll
                    for (int nt = 0; nt < 8; nt++) {
                        size_t off = (size_t)row * KVD + vh * HDIM + nt * 8 + cc;
                        *reinterpret_cast<__half2*>(vhi + off) =
                            __floats2half2_rn(acc[mt][nt][2*r], acc[mt][nt][2*r + 1]);
                    }
                }
            }
        }
    }
}

// ---------------- output projection kernel -----------------------------------
__global__ __launch_bounds__(GTHREADS)
void out_gemm(const __half* __restrict__ A, const __half* __restrict__ B,
              float* __restrict__ C)
{
    extern __shared__ char gsm[];
    const uint32_t sbase = smem_u32(gsm);

    const int tid  = threadIdx.x;
    const int wid  = tid >> 5;
    const int lane = tid & 31;
    const int bm   = blockIdx.y * BM;
    const int bn   = blockIdx.x * BN;
    const int wm   = (wid & 1) * 64;
    const int wn   = (wid >> 1) * 64;

    float acc[4][8][4];
    #pragma unroll
    for (int i = 0; i < 4; i++)
        #pragma unroll
        for (int j = 0; j < 8; j++)
            #pragma unroll
            for (int t = 0; t < 4; t++) acc[i][j][t] = 0.f;

    gemm_core(A + (size_t)bm * KDIM, B + bn, D_MODEL,
              sbase, tid, lane, wm, wn, acc);

    const int cr = lane >> 2;
    const int cc = (lane & 3) * 2;
    #pragma unroll
    for (int mt = 0; mt < 4; mt++) {
        #pragma unroll
        for (int nt = 0; nt < 8; nt++) {
            float* p0 = C + (size_t)(bm + wm + mt * 16 + cr) * D_MODEL + bn + wn + nt * 8 + cc;
            float* p1 = p0 + 8 * (size_t)D_MODEL;
            p0[0] = acc[mt][nt][0]; p0[1] = acc[mt][nt][1];
            p1[0] = acc[mt][nt][2]; p1[1] = acc[mt][nt][3];
        }
    }
}

// ---------------- HMMA causal GQA flash attention (unchanged from R14) -------
#define AT_STRB 144
#define KVBUF   (2 * 64 * AT_STRB)

__global__ __launch_bounds__(256, 2)
void attn_hmma(const __half* __restrict__ q16,
               const __half* __restrict__ khi, const __half* __restrict__ vhi,
               __half* __restrict__ chat)
{
    __shared__ __align__(16) char sm[2 * KVBUF];

    const int qb  = gridDim.x - 1 - blockIdx.x;
    const int h   = blockIdx.y;
    const int b   = blockIdx.z;
    const int kvh = h / GSIZE;
    const int tid = threadIdx.x;
    const int wid = tid >> 5;
    const int lane = tid & 31;
    const int qrow0 = qb * 128;
    const int wm = wid * 16;

    const uint32_t sbase = smem_u32(sm);
    const int VOFF = 64 * AT_STRB;

    {
        #pragma unroll
        for (int i = 0; i < 4; i++) {
            int u = tid + 256 * i;
            int row = u >> 3, seg = u & 7;
            uint4 v = *(const uint4*)(q16 + ((size_t)(b * S_LEN + qrow0 + row)) * D_MODEL
                                          + h * HDIM + seg * 8);
            *(uint4*)(sm + row * AT_STRB + seg * 16) = v;
        }
    }
    __syncthreads();

    uint32_t qh[4][4];
    {
        uint32_t arow = (uint32_t)(wm + (lane & 15));
        uint32_t koff = ((lane >> 4) & 1) * 8;
        #pragma unroll
        for (int kc = 0; kc < 4; kc++) {
            uint32_t a0 = sbase + arow * AT_STRB + (kc * 16 + koff) * 2;
            ldsm4(qh[kc][0], qh[kc][1], qh[kc][2], qh[kc][3], a0);
        }
    }
    __syncthreads();

    float m0 = -1e30f, m1 = -1e30f, l0 = 0.f, l1 = 0.f;
    float ctxa[8][4];
    #pragma unroll
    for (int t = 0; t < 8; t++)
        #pragma unroll
        for (int j = 0; j < 4; j++) ctxa[t][j] = 0.f;

    const int nkt = 2 * qb + 2;

    auto fillkv = [&](int kt, int buf) {
        const int k0 = kt * 64;
        const uint32_t base = sbase + buf * KVBUF;
        const __half* srcs[2] = {khi, vhi};
        #pragma unroll
        for (int arr = 0; arr < 2; arr++) {
            const __half* s = srcs[arr];
            #pragma unroll
            for (int i = 0; i < 2; i++) {
                int u = tid + 256 * i;
                int row = u >> 3, seg = u & 7;
                cp16(base + arr * VOFF + row * AT_STRB + seg * 16,
                     s + ((size_t)(b * S_LEN + k0 + row)) * KVD + kvh * HDIM + seg * 8);
            }
        }
    };

    fillkv(0, 0);
    CP_COMMIT();

    for (int kt = 0; kt < nkt; kt++) {
        const int k0 = kt * 64;
        const int buf = kt & 1;
        __syncthreads();
        if (kt + 1 < nkt) {
            fillkv(kt + 1, buf ^ 1);
            CP_COMMIT();
            CP_WAIT(1);
        } else {
            CP_WAIT(0);
        }
        __syncthreads();

        const uint32_t kvbase = sbase + buf * KVBUF;

        if (k0 <= qrow0 + wm + 15) {
            float sc[8][4];
            #pragma unroll
            for (int t = 0; t < 8; t++)
                #pragma unroll
                for (int j = 0; j < 4; j++) sc[t][j] = 0.f;

            #pragma unroll
            for (int g = 0; g < 4; g++) {
                uint32_t kh[4][4];
                #pragma unroll
                for (int kc = 0; kc < 4; kc++) {
                    uint32_t addr = kvbase
                        + (g * 16 + (lane & 7) + ((lane >> 4) & 1) * 8) * AT_STRB
                        + (kc * 16 + ((lane >> 3) & 1) * 8) * 2;
                    ldsm4(kh[kc][0], kh[kc][1], kh[kc][2], kh[kc][3], addr);
                }
                #pragma unroll
                for (int kc = 0; kc < 4; kc++) {
                    uint32_t bh0[2] = {kh[kc][0], kh[kc][1]};
                    uint32_t bh1[2] = {kh[kc][2], kh[kc][3]};
                    mma16816(sc[2*g],   qh[kc], bh0);
                    mma16816(sc[2*g+1], qh[kc], bh1);
                }
            }

            const int rtop = qrow0 + wm + (lane >> 2);
            const int rbot = rtop + 8;
            if (kt >= nkt - 2) {
                #pragma unroll
                for (int t = 0; t < 8; t++) {
                    int kg = k0 + t * 8 + (lane & 3) * 2;
                    if (kg     > rtop) sc[t][0] = -1e30f;
                    if (kg + 1 > rtop) sc[t][1] = -1e30f;
                    if (kg     > rbot) sc[t][2] = -1e30f;
                    if (kg + 1 > rbot) sc[t][3] = -1e30f;
                }
            }

            float tm0 = -1e30f, tm1 = -1e30f;
            #pragma unroll
            for (int t = 0; t < 8; t++) {
                tm0 = fmaxf(tm0, fmaxf(sc[t][0], sc[t][1]));
                tm1 = fmaxf(tm1, fmaxf(sc[t][2], sc[t][3]));
            }
            tm0 = fmaxf(tm0, __shfl_xor_sync(0xFFFFFFFFu, tm0, 1));
            tm0 = fmaxf(tm0, __shfl_xor_sync(0xFFFFFFFFu, tm0, 2));
            tm1 = fmaxf(tm1, __shfl_xor_sync(0xFFFFFFFFu, tm1, 1));
            tm1 = fmaxf(tm1, __shfl_xor_sync(0xFFFFFFFFu, tm1, 2));
            float mn0 = fmaxf(m0, tm0), mn1 = fmaxf(m1, tm1);
            float c0 = __expf(m0 - mn0), c1 = __expf(m1 - mn1);
            m0 = mn0; m1 = mn1;
            l0 *= c0;  l1 *= c1;
            #pragma unroll
            for (int t = 0; t < 8; t++) {
                ctxa[t][0] *= c0; ctxa[t][1] *= c0;
                ctxa[t][2] *= c1; ctxa[t][3] *= c1;
            }

            float ps0 = 0.f, ps1 = 0.f;
            uint32_t ph[4][4];
            #pragma unroll
            for (int t = 0; t < 8; t++) {
                float p0 = __expf(sc[t][0] - mn0);
                float p1 = __expf(sc[t][1] - mn0);
                float p2 = __expf(sc[t][2] - mn1);
                float p3 = __expf(sc[t][3] - mn1);
                ps0 += p0 + p1; ps1 += p2 + p3;
                int kc = t >> 1, hf = (t & 1) * 2;
                ph[kc][hf]     = pack2h(p0, p1);
                ph[kc][hf + 1] = pack2h(p2, p3);
            }
            ps0 += __shfl_xor_sync(0xFFFFFFFFu, ps0, 1);
            ps0 += __shfl_xor_sync(0xFFFFFFFFu, ps0, 2);
            ps1 += __shfl_xor_sync(0xFFFFFFFFu, ps1, 1);
            ps1 += __shfl_xor_sync(0xFFFFFFFFu, ps1, 2);
            l0 += ps0; l1 += ps1;

            #pragma unroll
            for (int kc = 0; kc < 4; kc++) {
                #pragma unroll
                for (int g = 0; g < 4; g++) {
                    uint32_t vh[4];
                    uint32_t addr = kvbase + VOFF
                        + (kc * 16 + (lane & 7) + ((lane >> 3) & 1) * 8) * AT_STRB
                        + (g * 16 + ((lane >> 4) & 1) * 8) * 2;
                    ldsm4t(vh[0], vh[1], vh[2], vh[3], addr);
                    uint32_t bh0[2] = {vh[0], vh[1]};
                    uint32_t bh1[2] = {vh[2], vh[3]};
                    mma16816(ctxa[2*g],   ph[kc], bh0);
                    mma16816(ctxa[2*g+1], ph[kc], bh1);
                }
            }
        }
    }

    float il0 = 1.f / l0, il1 = 1.f / l1;
    const int rtop = qrow0 + wm + (lane >> 2);
    const size_t row0 = (size_t)(b * S_LEN) + rtop;
    __half* c0p = chat + row0 * KDIM + h * HDIM;
    __half* c1p = c0p + 8 * (size_t)KDIM;
    #pragma unroll
    for (int t = 0; t < 8; t++) {
        int col = t * 8 + (lane & 3) * 2;
        *reinterpret_cast<__half2*>(c0p + col) =
            __floats2half2_rn(ctxa[t][0] * il0, ctxa[t][1] * il0);
        *reinterpret_cast<__half2*>(c1p + col) =
            __floats2half2_rn(ctxa[t][2] * il1, ctxa[t][3] * il1);
    }
}

// ---------------- host launch -------------------------------------------------
extern "C" void kernel_launch(void* const* d_in, const int* in_sizes, int n_in,
                              void* d_out, int out_size)
{
    const float* x  = (const float*)d_in[0];
    const float* Wq = (const float*)d_in[1];
    const float* Wk = (const float*)d_in[2];
    const float* Wv = (const float*)d_in[3];
    const float* Wo = (const float*)d_in[4];
    float* out = (float*)d_out;

    __half *ahat, *chat, *wq, *wkv, *wo, *q16, *khi, *vhi;
    cudaGetSymbolAddress((void**)&ahat, g_ahat);
    cudaGetSymbolAddress((void**)&chat, g_chat);
    cudaGetSymbolAddress((void**)&wq,   g_wq);
    cudaGetSymbolAddress((void**)&wkv,  g_wkv);
    cudaGetSymbolAddress((void**)&wo,   g_wo);
    cudaGetSymbolAddress((void**)&q16,  g_q16);
    cudaGetSymbolAddress((void**)&khi,  g_khi);
    cudaGetSymbolAddress((void**)&vhi,  g_vhi);

    static int smem_set = 0;
    if (!smem_set) {
        cudaFuncSetAttribute(qkv_gemm, cudaFuncAttributeMaxDynamicSharedMemorySize, GSMEM);
        cudaFuncSetAttribute(out_gemm, cudaFuncAttributeMaxDynamicSharedMemorySize, GSMEM);
        smem_set = 1;
    }

    // streaming prep (all conversions coalesced, no transposes)
    prep<<<PREP_BLOCKS, 256>>>(x, Wq, Wk, Wv, Wo, ahat, wq, wkv, wo);

    // fused Q + KV projection (24 n-tiles: 16 Q + 8 KV), K = 2048
    qkv_gemm<<<dim3((D_MODEL + NKV2) / BN, MROWS / BM), GTHREADS, GSMEM>>>(
        ahat, wq, wkv, q16, khi, vhi);

    // attention (all fp16 operands)
    attn_hmma<<<dim3(S_LEN / 128, NHEADS, BATCH), 256>>>(q16, khi, vhi, chat);

    // output projection (K = 2048)
    out_gemm<<<dim3(D_MODEL / BN, MROWS / BM), GTHREADS, GSMEM>>>(chat, wo, out);
}

// round 16
// speedup vs baseline: 1.0523x; 1.0523x over previous
#include <cuda_runtime.h>
#include <cuda_fp16.h>
#include <math.h>
#include <cstdint>

#define BATCH   2
#define S_LEN   2048
#define D_MODEL 2048
#define NHEADS  32
#define NKVH    8
#define HDIM    64
#define GSIZE   (NHEADS / NKVH)
#define KVD     (NKVH * HDIM)        // 512
#define MROWS   (BATCH * S_LEN)      // 4096
#define KDIM    2048
#define NKV2    (2 * KVD)            // 1024 fused K|V width

// ---------------- scratch (device globals) ----------------------------------
__device__ __half g_ahat[(size_t)MROWS  * KDIM];    // x fp16
__device__ __half g_chat[(size_t)MROWS  * KDIM];    // ctx fp16
__device__ __half g_wq [(size_t)D_MODEL * KDIM];    // transposed [N][K]
__device__ __half g_wkv[(size_t)NKV2    * KDIM];
__device__ __half g_wo [(size_t)D_MODEL * KDIM];
__device__ float g_cos[S_LEN * 32];
__device__ float g_sin[S_LEN * 32];
__device__ __half g_q16[MROWS * D_MODEL];
__device__ __half g_khi[MROWS * KVD];
__device__ __half g_vhi[MROWS * KVD];

// ---------------- helpers ------------------------------------------------
__device__ __forceinline__ uint32_t smem_u32(const void* p) {
    uint32_t a;
    asm("{ .reg .u64 t; cvta.to.shared.u64 t, %1; cvt.u32.u64 %0, t; }"
        : "=r"(a) : "l"(p));
    return a;
}

__device__ __forceinline__ void cp16(uint32_t saddr, const void* gaddr) {
    asm volatile("cp.async.cg.shared.global [%0], [%1], 16;"
                 :: "r"(saddr), "l"(gaddr) : "memory");
}
#define CP_COMMIT() asm volatile("cp.async.commit_group;" ::: "memory")
#define CP_WAIT(n)  asm volatile("cp.async.wait_group %0;" :: "n"(n) : "memory")

__device__ __forceinline__ void ldsm4(uint32_t& r0, uint32_t& r1, uint32_t& r2,
                                      uint32_t& r3, uint32_t addr) {
    asm volatile("ldmatrix.sync.aligned.m8n8.x4.shared.b16 {%0,%1,%2,%3}, [%4];"
                 : "=r"(r0), "=r"(r1), "=r"(r2), "=r"(r3) : "r"(addr));
}
__device__ __forceinline__ void ldsm4t(uint32_t& r0, uint32_t& r1, uint32_t& r2,
                                       uint32_t& r3, uint32_t addr) {
    asm volatile("ldmatrix.sync.aligned.m8n8.x4.trans.shared.b16 {%0,%1,%2,%3}, [%4];"
                 : "=r"(r0), "=r"(r1), "=r"(r2), "=r"(r3) : "r"(addr));
}

__device__ __forceinline__ void mma16816(float* d, const uint32_t* a, const uint32_t* b) {
    asm volatile(
        "mma.sync.aligned.m16n8k16.row.col.f32.f16.f16.f32 "
        "{%0,%1,%2,%3}, {%4,%5,%6,%7}, {%8,%9}, {%0,%1,%2,%3};"
        : "+f"(d[0]), "+f"(d[1]), "+f"(d[2]), "+f"(d[3])
        : "r"(a[0]), "r"(a[1]), "r"(a[2]), "r"(a[3]), "r"(b[0]), "r"(b[1]));
}

__device__ __forceinline__ uint32_t pack2h(float lo_e, float hi_e) {
    __half2 h = __floats2half2_rn(lo_e, hi_e);
    return *reinterpret_cast<uint32_t*>(&h);
}

// ---------------- fused prep kernel -------------------------------------------
// x conversion vectorized: float4 in, 2x half2 out (4 elems/thread).
#define PREP_X_BLOCKS 8192                 // 8192*256*4 = 8,388,608 elems
#define PREP_ROPE_BLOCKS 256
#define PREP_BLOCKS (PREP_X_BLOCKS + PREP_ROPE_BLOCKS + 10240)

__device__ __forceinline__ void wt_body(const float* __restrict__ W,
                                        __half* __restrict__ out, int N,
                                        int bx, int by, float tile[32][33])
{
    int tx = threadIdx.x & 31, tg = threadIdx.x >> 5;
    int k0 = by * 32, n0 = bx * 32;
    #pragma unroll
    for (int i = 0; i < 4; i++) {
        int ty = tg * 4 + i;
        tile[ty][tx] = W[(size_t)(k0 + ty) * N + n0 + tx];
    }
    __syncthreads();
    #pragma unroll
    for (int i = 0; i < 4; i++) {
        int ty = tg * 4 + i;
        out[(size_t)(n0 + ty) * KDIM + k0 + tx] = __float2half_rn(tile[tx][ty]);
    }
}

__global__ __launch_bounds__(256)
void prep(const float* __restrict__ x,
          const float* __restrict__ Wq, const float* __restrict__ Wk,
          const float* __restrict__ Wv, const float* __restrict__ Wo,
          __half* __restrict__ ahat, __half* __restrict__ wq,
          __half* __restrict__ wkv, __half* __restrict__ wo)
{
    __shared__ float tile[32][33];
    const int bid = blockIdx.x;
    const int tid = threadIdx.x;

    if (bid < PREP_X_BLOCKS) {
        int i = (bid * 256 + tid) * 4;
        float4 v = *reinterpret_cast<const float4*>(x + i);
        *reinterpret_cast<__half2*>(ahat + i)     = __floats2half2_rn(v.x, v.y);
        *reinterpret_cast<__half2*>(ahat + i + 2) = __floats2half2_rn(v.z, v.w);
    } else if (bid < PREP_X_BLOCKS + PREP_ROPE_BLOCKS) {
        int i = (bid - PREP_X_BLOCKS) * 256 + tid;
        int s = i >> 5, j = i & 31;
        float inv = (float)exp(-(double)j * (log(10000.0) / 32.0));
        float ang = (float)s * inv;
        float c, sn;
        sincosf(ang, &sn, &c);
        g_cos[i] = c;
        g_sin[i] = sn;
    } else {
        int idx = bid - (PREP_X_BLOCKS + PREP_ROPE_BLOCKS);
        if (idx < 4096) {
            wt_body(Wq, wq, D_MODEL, idx & 63, idx >> 6, tile);
        } else if (idx < 5120) {
            int l = idx - 4096;
            wt_body(Wk, wkv, KVD, l & 15, l >> 4, tile);
        } else if (idx < 6144) {
            int l = idx - 5120;
            wt_body(Wv, wkv + (size_t)KVD * KDIM, KVD, l & 15, l >> 4, tile);
        } else {
            int l = idx - 6144;
            wt_body(Wo, wo, D_MODEL, l & 63, l >> 6, tile);
        }
    }
}

// ---------------- GEMM core ----------------------------------------------------
// 128x128 CTA, 4 warps (2M x 2N), warp tile 64x64, KC=64, 3 stages, 128 threads.
#define BM 128
#define BN 128
#define KC 64
#define STAGES 3
#define RSB    144
#define STG_A  (128 * RSB)
#define STG_SZ (2 * STG_A)
#define GSMEM  (STAGES * STG_SZ)     // 110592
#define GTHREADS 128

__device__ __forceinline__ void gemm_core(
    const __half* __restrict__ Ab, const __half* __restrict__ Bb,
    uint32_t sbase, int tid, int lane, int wm, int wn, float acc[4][8][4])
{
    constexpr int NCHUNK = KDIM / KC;

    const int a_row  = wm + (lane & 15);
    const int a_koff = ((lane >> 4) & 1) * 8;
    const int b_row_base = wn + (lane & 7) + ((lane >> 4) & 1) * 8;
    const int b_koff = ((lane >> 3) & 1) * 8;

    auto fill = [&](int c, int slot) {
        const int kpos = c * KC;
        const uint32_t abase = sbase + slot * STG_SZ;
        const uint32_t bbase = abase + STG_A;
        #pragma unroll
        for (int i = 0; i < 8; i++) {
            int u = tid + GTHREADS * i;
            int row = u >> 3, seg = u & 7;
            cp16(abase + row * RSB + seg * 16, Ab + (size_t)row * KDIM + kpos + seg * 8);
            cp16(bbase + row * RSB + seg * 16, Bb + (size_t)row * KDIM + kpos + seg * 8);
        }
    };

    #pragma unroll
    for (int s = 0; s < STAGES - 1; s++) {
        fill(s, s);
        CP_COMMIT();
    }

    for (int c = 0; c < NCHUNK; c++) {
        CP_WAIT(STAGES - 2);
        __syncthreads();

        if (c + STAGES - 1 < NCHUNK)
            fill(c + STAGES - 1, (c + STAGES - 1) % STAGES);
        CP_COMMIT();

        const int slot = c % STAGES;
        const uint32_t abase = sbase + slot * STG_SZ;
        const uint32_t bbase = abase + STG_A;
        #pragma unroll
        for (int ks = 0; ks < 4; ks++) {
            const int kp = ks * 16;
            uint32_t af[4][4];
            #pragma unroll
            for (int mt = 0; mt < 4; mt++) {
                uint32_t addr = abase + (a_row + mt * 16) * RSB + (kp + a_koff) * 2;
                ldsm4(af[mt][0], af[mt][1], af[mt][2], af[mt][3], addr);
            }
            uint32_t bf[8][2];
            #pragma unroll
            for (int bt = 0; bt < 4; bt++) {
                uint32_t addr = bbase + (b_row_base + bt * 16) * RSB + (kp + b_koff) * 2;
                ldsm4(bf[2*bt][0], bf[2*bt][1], bf[2*bt+1][0], bf[2*bt+1][1], addr);
            }
            #pragma unroll
            for (int mt = 0; mt < 4; mt++)
                #pragma unroll
                for (int nt = 0; nt < 8; nt++)
                    mma16816(acc[mt][nt], af[mt], bf[nt]);
        }
    }
}

// ---------------- fused QKV projection kernel --------------------------------
__global__ __launch_bounds__(GTHREADS)
void qkv_gemm(const __half* __restrict__ A,
              const __half* __restrict__ Wq, const __half* __restrict__ Wkv,
              __half* __restrict__ q16,
              __half* __restrict__ khi, __half* __restrict__ vhi)
{
    extern __shared__ char gsm[];
    const uint32_t sbase = smem_u32(gsm);

    const int tid  = threadIdx.x;
    const int wid  = tid >> 5;
    const int lane = tid & 31;
    const int bm   = blockIdx.y * BM;
    const bool isQ = blockIdx.x < (D_MODEL / BN);
    const int bn   = (isQ ? blockIdx.x : blockIdx.x - D_MODEL / BN) * BN;
    const int wm   = (wid & 1) * 64;
    const int wn   = (wid >> 1) * 64;

    float acc[4][8][4];
    #pragma unroll
    for (int i = 0; i < 4; i++)
        #pragma unroll
        for (int j = 0; j < 8; j++)
            #pragma unroll
            for (int t = 0; t < 4; t++) acc[i][j][t] = 0.f;

    const __half* Ab = A + (size_t)bm * KDIM;
    const __half* Bb = (isQ ? Wq : Wkv) + (size_t)bn * KDIM;

    gemm_core(Ab, Bb, sbase, tid, lane, wm, wn, acc);

    const int cr = lane >> 2;
    const int cc = (lane & 3) * 2;

    if (isQ) {
        const int head = (bn + wn) >> 6;
        #pragma unroll
        for (int mt = 0; mt < 4; mt++) {
            #pragma unroll
            for (int r = 0; r < 2; r++) {
                const int row = bm + wm + mt * 16 + cr + r * 8;
                const int s = row & (S_LEN - 1);
                #pragma unroll
                for (int nt = 0; nt < 4; nt++) {
                    const int j = nt * 8 + cc;
                    float c0 = g_cos[(s << 5) + j],     sn0 = g_sin[(s << 5) + j];
                    float c1 = g_cos[(s << 5) + j + 1], sn1 = g_sin[(s << 5) + j + 1];
                    float x1a = acc[mt][nt][2*r],     x1b = acc[mt][nt][2*r + 1];
                    float x2a = acc[mt][nt+4][2*r],   x2b = acc[mt][nt+4][2*r + 1];
                    float y1a = (x1a * c0 - x2a * sn0) * 0.125f;
                    float y1b = (x1b * c1 - x2b * sn1) * 0.125f;
                    float y2a = (x2a * c0 + x1a * sn0) * 0.125f;
                    float y2b = (x2b * c1 + x1b * sn1) * 0.125f;
                    size_t off = (size_t)row * D_MODEL + head * HDIM + j;
                    *reinterpret_cast<__half2*>(q16 + off)      = __floats2half2_rn(y1a, y1b);
                    *reinterpret_cast<__half2*>(q16 + off + 32) = __floats2half2_rn(y2a, y2b);
                }
            }
        }
    } else {
        const int hh = (bn + wn) >> 6;
        if (hh < NKVH) {
            #pragma unroll
            for (int mt = 0; mt < 4; mt++) {
                #pragma unroll
                for (int r = 0; r < 2; r++) {
                    const int row = bm + wm + mt * 16 + cr + r * 8;
                    const int s = row & (S_LEN - 1);
                    #pragma unroll
                    for (int nt = 0; nt < 4; nt++) {
                        const int j = nt * 8 + cc;
                        float c0 = g_cos[(s << 5) + j],     sn0 = g_sin[(s << 5) + j];
                        float c1 = g_cos[(s << 5) + j + 1], sn1 = g_sin[(s << 5) + j + 1];
                        float x1a = acc[mt][nt][2*r],   x1b = acc[mt][nt][2*r + 1];
                        float x2a = acc[mt][nt+4][2*r], x2b = acc[mt][nt+4][2*r + 1];
                        size_t off = (size_t)row * KVD + hh * HDIM + j;
                        *reinterpret_cast<__half2*>(khi + off) =
                            __floats2half2_rn(x1a * c0 - x2a * sn0, x1b * c1 - x2b * sn1);
                        *reinterpret_cast<__half2*>(khi + off + 32) =
                            __floats2half2_rn(x2a * c0 + x1a * sn0, x2b * c1 + x1b * sn1);
                    }
                }
            }
        } else {
            const int vh = hh - NKVH;
            #pragma unroll
            for (int mt = 0; mt < 4; mt++) {
                #pragma unroll
                for (int r = 0; r < 2; r++) {
                    const int row = bm + wm + mt * 16 + cr + r * 8;
                    #pragma unroll
                    for (int nt = 0; nt < 8; nt++) {
                        size_t off = (size_t)row * KVD + vh * HDIM + nt * 8 + cc;
                        *reinterpret_cast<__half2*>(vhi + off) =
                            __floats2half2_rn(acc[mt][nt][2*r], acc[mt][nt][2*r + 1]);
                    }
                }
            }
        }
    }
}

// ---------------- output projection kernel -----------------------------------
__global__ __launch_bounds__(GTHREADS)
void out_gemm(const __half* __restrict__ A, const __half* __restrict__ B,
              float* __restrict__ C)
{
    extern __shared__ char gsm[];
    const uint32_t sbase = smem_u32(gsm);

    const int tid  = threadIdx.x;
    const int wid  = tid >> 5;
    const int lane = tid & 31;
    const int bm   = blockIdx.y * BM;
    const int bn   = blockIdx.x * BN;
    const int wm   = (wid & 1) * 64;
    const int wn   = (wid >> 1) * 64;

    float acc[4][8][4];
    #pragma unroll
    for (int i = 0; i < 4; i++)
        #pragma unroll
        for (int j = 0; j < 8; j++)
            #pragma unroll
            for (int t = 0; t < 4; t++) acc[i][j][t] = 0.f;

    gemm_core(A + (size_t)bm * KDIM, B + (size_t)bn * KDIM,
              sbase, tid, lane, wm, wn, acc);

    const int cr = lane >> 2;
    const int cc = (lane & 3) * 2;
    #pragma unroll
    for (int mt = 0; mt < 4; mt++) {
        #pragma unroll
        for (int nt = 0; nt < 8; nt++) {
            float* p0 = C + (size_t)(bm + wm + mt * 16 + cr) * D_MODEL + bn + wn + nt * 8 + cc;
            float* p1 = p0 + 8 * (size_t)D_MODEL;
            p0[0] = acc[mt][nt][0]; p0[1] = acc[mt][nt][1];
            p1[0] = acc[mt][nt][2]; p1[1] = acc[mt][nt][3];
        }
    }
}

// ---------------- HMMA causal GQA flash attention ----------------------------
#define AT_STRB 144
#define KVBUF   (2 * 64 * AT_STRB)

__global__ __launch_bounds__(256, 2)
void attn_hmma(const __half* __restrict__ q16,
               const __half* __restrict__ khi, const __half* __restrict__ vhi,
               __half* __restrict__ chat)
{
    __shared__ __align__(16) char sm[2 * KVBUF];

    const int qb  = gridDim.x - 1 - blockIdx.x;
    const int h   = blockIdx.y;
    const int b   = blockIdx.z;
    const int kvh = h / GSIZE;
    const int tid = threadIdx.x;
    const int wid = tid >> 5;
    const int lane = tid & 31;
    const int qrow0 = qb * 128;
    const int wm = wid * 16;

    const uint32_t sbase = smem_u32(sm);
    const int VOFF = 64 * AT_STRB;

    {
        #pragma unroll
        for (int i = 0; i < 4; i++) {
            int u = tid + 256 * i;
            int row = u >> 3, seg = u & 7;
            uint4 v = *(const uint4*)(q16 + ((size_t)(b * S_LEN + qrow0 + row)) * D_MODEL
                                          + h * HDIM + seg * 8);
            *(uint4*)(sm + row * AT_STRB + seg * 16) = v;
        }
    }
    __syncthreads();

    uint32_t qh[4][4];
    {
        uint32_t arow = (uint32_t)(wm + (lane & 15));
        uint32_t koff = ((lane >> 4) & 1) * 8;
        #pragma unroll
        for (int kc = 0; kc < 4; kc++) {
            uint32_t a0 = sbase + arow * AT_STRB + (kc * 16 + koff) * 2;
            ldsm4(qh[kc][0], qh[kc][1], qh[kc][2], qh[kc][3], a0);
        }
    }
    __syncthreads();

    float m0 = -1e30f, m1 = -1e30f, l0 = 0.f, l1 = 0.f;
    float ctxa[8][4];
    #pragma unroll
    for (int t = 0; t < 8; t++)
        #pragma unroll
        for (int j = 0; j < 4; j++) ctxa[t][j] = 0.f;

    const int nkt = 2 * qb + 2;

    auto fillkv = [&](int kt, int buf) {
        const int k0 = kt * 64;
        const uint32_t base = sbase + buf * KVBUF;
        const __half* srcs[2] = {khi, vhi};
        #pragma unroll
        for (int arr = 0; arr < 2; arr++) {
            const __half* s = srcs[arr];
            #pragma unroll
            for (int i = 0; i < 2; i++) {
                int u = tid + 256 * i;
                int row = u >> 3, seg = u & 7;
                cp16(base + arr * VOFF + row * AT_STRB + seg * 16,
                     s + ((size_t)(b * S_LEN + k0 + row)) * KVD + kvh * HDIM + seg * 8);
            }
        }
    };

    fillkv(0, 0);
    CP_COMMIT();

    for (int kt = 0; kt < nkt; kt++) {
        const int k0 = kt * 64;
        const int buf = kt & 1;
        __syncthreads();
        if (kt + 1 < nkt) {
            fillkv(kt + 1, buf ^ 1);
            CP_COMMIT();
            CP_WAIT(1);
        } else {
            CP_WAIT(0);
        }
        __syncthreads();

        const uint32_t kvbase = sbase + buf * KVBUF;

        if (k0 <= qrow0 + wm + 15) {
            float sc[8][4];
            #pragma unroll
            for (int t = 0; t < 8; t++)
                #pragma unroll
                for (int j = 0; j < 4; j++) sc[t][j] = 0.f;

            #pragma unroll
            for (int g = 0; g < 4; g++) {
                uint32_t kh[4][4];
                #pragma unroll
                for (int kc = 0; kc < 4; kc++) {
                    uint32_t addr = kvbase
                        + (g * 16 + (lane & 7) + ((lane >> 4) & 1) * 8) * AT_STRB
                        + (kc * 16 + ((lane >> 3) & 1) * 8) * 2;
                    ldsm4(kh[kc][0], kh[kc][1], kh[kc][2], kh[kc][3], addr);
                }
                #pragma unroll
                for (int kc = 0; kc < 4; kc++) {
                    uint32_t bh0[2] = {kh[kc][0], kh[kc][1]};
                    uint32_t bh1[2] = {kh[kc][2], kh[kc][3]};
                    mma16816(sc[2*g],   qh[kc], bh0);
                    mma16816(sc[2*g+1], qh[kc], bh1);
                }
            }

            const int rtop = qrow0 + wm + (lane >> 2);
            const int rbot = rtop + 8;
            if (kt >= nkt - 2) {
                #pragma unroll
                for (int t = 0; t < 8; t++) {
                    int kg = k0 + t * 8 + (lane & 3) * 2;
                    if (kg     > rtop) sc[t][0] = -1e30f;
                    if (kg + 1 > rtop) sc[t][1] = -1e30f;
                    if (kg     > rbot) sc[t][2] = -1e30f;
                    if (kg + 1 > rbot) sc[t][3] = -1e30f;
                }
            }

            float tm0 = -1e30f, tm1 = -1e30f;
            #pragma unroll
            for (int t = 0; t < 8; t++) {
                tm0 = fmaxf(tm0, fmaxf(sc[t][0], sc[t][1]));
                tm1 = fmaxf(tm1, fmaxf(sc[t][2], sc[t][3]));
            }
            tm0 = fmaxf(tm0, __shfl_xor_sync(0xFFFFFFFFu, tm0, 1));
            tm0 = fmaxf(tm0, __shfl_xor_sync(0xFFFFFFFFu, tm0, 2));
            tm1 = fmaxf(tm1, __shfl_xor_sync(0xFFFFFFFFu, tm1, 1));
            tm1 = fmaxf(tm1, __shfl_xor_sync(0xFFFFFFFFu, tm1, 2));
            float mn0 = fmaxf(m0, tm0), mn1 = fmaxf(m1, tm1);
            float c0 = __expf(m0 - mn0), c1 = __expf(m1 - mn1);
            m0 = mn0; m1 = mn1;
            l0 *= c0;  l1 *= c1;
            #pragma unroll
            for (int t = 0; t < 8; t++) {
                ctxa[t][0] *= c0; ctxa[t][1] *= c0;
                ctxa[t][2] *= c1; ctxa[t][3] *= c1;
            }

            float ps0 = 0.f, ps1 = 0.f;
            uint32_t ph[4][4];
            #pragma unroll
            for (int t = 0; t < 8; t++) {
                float p0 = __expf(sc[t][0] - mn0);
                float p1 = __expf(sc[t][1] - mn0);
                float p2 = __expf(sc[t][2] - mn1);
                float p3 = __expf(sc[t][3] - mn1);
                ps0 += p0 + p1; ps1 += p2 + p3;
                int kc = t >> 1, hf = (t & 1) * 2;
                ph[kc][hf]     = pack2h(p0, p1);
                ph[kc][hf + 1] = pack2h(p2, p3);
            }
            ps0 += __shfl_xor_sync(0xFFFFFFFFu, ps0, 1);
            ps0 += __shfl_xor_sync(0xFFFFFFFFu, ps0, 2);
            ps1 += __shfl_xor_sync(0xFFFFFFFFu, ps1, 1);
            ps1 += __shfl_xor_sync(0xFFFFFFFFu, ps1, 2);
            l0 += ps0; l1 += ps1;

            #pragma unroll
            for (int kc = 0; kc < 4; kc++) {
                #pragma unroll
                for (int g = 0; g < 4; g++) {
                    uint32_t vh[4];
                    uint32_t addr = kvbase + VOFF
                        + (kc * 16 + (lane & 7) + ((lane >> 3) & 1) * 8) * AT_STRB
                        + (g * 16 + ((lane >> 4) & 1) * 8) * 2;
                    ldsm4t(vh[0], vh[1], vh[2], vh[3], addr);
                    uint32_t bh0[2] = {vh[0], vh[1]};
                    uint32_t bh1[2] = {vh[2], vh[3]};
                    mma16816(ctxa[2*g],   ph[kc], bh0);
                    mma16816(ctxa[2*g+1], ph[kc], bh1);
                }
            }
        }
    }

    float il0 = 1.f / l0, il1 = 1.f / l1;
    const int rtop = qrow0 + wm + (lane >> 2);
    const size_t row0 = (size_t)(b * S_LEN) + rtop;
    __half* c0p = chat + row0 * KDIM + h * HDIM;
    __half* c1p = c0p + 8 * (size_t)KDIM;
    #pragma unroll
    for (int t = 0; t < 8; t++) {
        int col = t * 8 + (lane & 3) * 2;
        *reinterpret_cast<__half2*>(c0p + col) =
            __floats2half2_rn(ctxa[t][0] * il0, ctxa[t][1] * il0);
        *reinterpret_cast<__half2*>(c1p + col) =
            __floats2half2_rn(ctxa[t][2] * il1, ctxa[t][3] * il1);
    }
}

// ---------------- host launch -------------------------------------------------
extern "C" void kernel_launch(void* const* d_in, const int* in_sizes, int n_in,
                              void* d_out, int out_size)
{
    const float* x  = (const float*)d_in[0];
    const float* Wq = (const float*)d_in[1];
    const float* Wk = (const float*)d_in[2];
    const float* Wv = (const float*)d_in[3];
    const float* Wo = (const float*)d_in[4];
    float* out = (float*)d_out;

    __half *ahat, *chat, *wq, *wkv, *wo, *q16, *khi, *vhi;
    cudaGetSymbolAddress((void**)&ahat, g_ahat);
    cudaGetSymbolAddress((void**)&chat, g_chat);
    cudaGetSymbolAddress((void**)&wq,   g_wq);
    cudaGetSymbolAddress((void**)&wkv,  g_wkv);
    cudaGetSymbolAddress((void**)&wo,   g_wo);
    cudaGetSymbolAddress((void**)&q16,  g_q16);
    cudaGetSymbolAddress((void**)&khi,  g_khi);
    cudaGetSymbolAddress((void**)&vhi,  g_vhi);

    static int smem_set = 0;
    if (!smem_set) {
        cudaFuncSetAttribute(qkv_gemm, cudaFuncAttributeMaxDynamicSharedMemorySize, GSMEM);
        cudaFuncSetAttribute(out_gemm, cudaFuncAttributeMaxDynamicSharedMemorySize, GSMEM);
        smem_set = 1;
    }

    // fused prep (vectorized x conversion + rope table + weight transposes)
    prep<<<PREP_BLOCKS, 256>>>(x, Wq, Wk, Wv, Wo, ahat, wq, wkv, wo);

    // fused Q + KV projection (24 n-tiles: 16 Q + 8 KV), K = 2048
    qkv_gemm<<<dim3((D_MODEL + NKV2) / BN, MROWS / BM), GTHREADS, GSMEM>>>(
        ahat, wq, wkv, q16, khi, vhi);

    // attention (all fp16 operands)
    attn_hmma<<<dim3(S_LEN / 128, NHEADS, BATCH), 256>>>(q16, khi, vhi, chat);

    // output projection (K = 2048)
    out_gemm<<<dim3(D_MODEL / BN, MROWS / BM), GTHREADS, GSMEM>>>(chat, wo, out);
}